// round 3
// baseline (speedup 1.0000x reference)
#include <cuda_runtime.h>
#include <cuda_bf16.h>

// Problem constants
#define BB   4
#define HH   160
#define WW   288
#define HO   80
#define WO   144
#define HWO  (HO*WO)     // 11520
#define DMAX 24
#define EPSV 1e-5f

// Scratch (no allocation allowed -> __device__ globals)
__device__ float d_gy[BB*192*HWO];   // gwc conv1+bn+lrelu output (4,192,80,144)
__device__ float d_cy[BB*24*HWO];    // cat conv1+bn+lrelu output (4,24,80,144)
__device__ float d_g8[BB*96*HWO];    // gwc downsampled features  (4,96,80,144)
__device__ float d_c8[BB*12*HWO];    // cat downsampled features  (4,12,80,144)

// ---- packed f32x2 helpers (sm_100+) ---------------------------------------
__device__ __forceinline__ unsigned long long pack2(float v) {
    unsigned long long r;
    asm("mov.b64 %0, {%1, %1};" : "=l"(r) : "f"(v));
    return r;
}
__device__ __forceinline__ void ffma2(unsigned long long& acc,
                                      unsigned long long a,
                                      unsigned long long b) {
    asm("fma.rn.f32x2 %0, %1, %2, %0;" : "+l"(acc) : "l"(a), "l"(b));
}
__device__ __forceinline__ void unpack2(unsigned long long v, float& lo, float& hi) {
    asm("mov.b64 {%0, %1}, %2;" : "=f"(lo), "=f"(hi) : "l"(v));
}

// ---------------------------------------------------------------------------
// Kernel 1: 3x3 stride-2 pad-1 conv + BN + LeakyReLU(0.1)
// Tile: 8x16 output pixels, OCB output channels per block, ic chunks of 4.
// Thread: OCT=OCB/8 oc x 4 pixels, packed f32x2 FMA over oc pairs, kw-reuse
// of the 9 input values per (ic, kh).
// ---------------------------------------------------------------------------
template<int CIN, int COUT, int OCB>
__global__ __launch_bounds__(256)
void conv1_bn_lrelu(const float* __restrict__ x, const float* __restrict__ w,
                    const float* __restrict__ bng, const float* __restrict__ bnb,
                    const float* __restrict__ bnm, const float* __restrict__ bnv,
                    float* __restrict__ y)
{
    constexpr int NOC = (COUT + OCB - 1) / OCB;
    constexpr int OCT = OCB / 8;        // oc per thread
    constexpr int NP  = OCT / 2;        // oc pairs per thread

    const int bz      = blockIdx.z;
    const int b       = bz / NOC;
    const int oc_base = (bz % NOC) * OCB;
    const int oh0 = blockIdx.y * 8;
    const int ow0 = blockIdx.x * 16;
    const int ih0 = oh0 * 2 - 1;
    const int iw0 = ow0 * 2 - 1;

    __shared__ __align__(16) float in_s[4 * 17 * 33];     // 4 ic x 17h x 33w
    __shared__ __align__(16) float w_s[4 * 9 * OCB];      // [ic*9+tap][oc_local]

    const int tid = threadIdx.x;
    const int og  = tid >> 5;           // 0..7 -> oc group
    const int pq  = tid & 31;           // pixel group of 4 (along w)
    const int ph  = pq >> 2;            // 0..7
    const int pw0 = (pq & 3) * 4;       // 0,4,8,12

    unsigned long long acc2[NP][4];
    #pragma unroll
    for (int k = 0; k < NP; ++k)
        #pragma unroll
        for (int j = 0; j < 4; ++j) acc2[k][j] = 0ull;

    for (int ic0 = 0; ic0 < CIN; ic0 += 4) {
        // cooperative input patch load (zero padded borders)
        #pragma unroll
        for (int ic = 0; ic < 4; ++ic) {
            const float* xp = x + (((size_t)b * CIN + ic0 + ic) * HH) * WW;
            for (int j = tid; j < 561; j += 256) {
                int ih = j / 33, iw = j % 33;
                int gh = ih0 + ih, gw = iw0 + iw;
                float v = 0.f;
                if ((unsigned)gh < (unsigned)HH && (unsigned)gw < (unsigned)WW)
                    v = xp[gh * WW + gw];
                in_s[ic * 561 + j] = v;
            }
        }
        // cooperative weight load, oc-fastest layout
        for (int idx = tid; idx < 36 * OCB; idx += 256) {
            int oc_l = idx & (OCB - 1);
            int r    = idx / OCB;               // ic*9 + tap
            int ic   = r / 9, tap = r % 9;
            int oc_g = oc_base + oc_l;
            float v  = 0.f;
            if (oc_g < COUT) v = w[((size_t)oc_g * CIN + ic0 + ic) * 9 + tap];
            w_s[r * OCB + oc_l] = v;
        }
        __syncthreads();

        #pragma unroll
        for (int ic = 0; ic < 4; ++ic) {
            #pragma unroll
            for (int kh = 0; kh < 3; ++kh) {
                const float* ip = &in_s[ic * 561 + (ph * 2 + kh) * 33 + pw0 * 2];
                float iv[9];
                #pragma unroll
                for (int c = 0; c < 9; ++c) iv[c] = ip[c];
                #pragma unroll
                for (int kw = 0; kw < 3; ++kw) {
                    unsigned long long ipk[4];
                    #pragma unroll
                    for (int j = 0; j < 4; ++j) ipk[j] = pack2(iv[2 * j + kw]);
                    const unsigned long long* wp = (const unsigned long long*)
                        &w_s[(ic * 9 + kh * 3 + kw) * OCB + og * OCT];
                    #pragma unroll
                    for (int k = 0; k < NP; ++k) {
                        unsigned long long wv = wp[k];
                        #pragma unroll
                        for (int j = 0; j < 4; ++j) ffma2(acc2[k][j], wv, ipk[j]);
                    }
                }
            }
        }
        __syncthreads();
    }

    // BN + LeakyReLU epilogue
    #pragma unroll
    for (int k = 0; k < NP; ++k) {
        #pragma unroll
        for (int half = 0; half < 2; ++half) {
            int oc_g = oc_base + og * OCT + 2 * k + half;
            if (oc_g < COUT) {
                float sc = bng[oc_g] * rsqrtf(bnv[oc_g] + EPSV);
                float sh = bnb[oc_g] - bnm[oc_g] * sc;
                float* yp = y + (((size_t)b * COUT + oc_g) * HO + oh0 + ph) * WO
                              + ow0 + pw0;
                #pragma unroll
                for (int j = 0; j < 4; ++j) {
                    float lo, hi;
                    unpack2(acc2[k][j], lo, hi);
                    float a = half ? hi : lo;
                    float v = a * sc + sh;
                    v = (v >= 0.f) ? v : 0.1f * v;
                    yp[j] = v;
                }
            }
        }
    }
}

// ---------------------------------------------------------------------------
// Kernel 2: fused 1x1 conv (mask logits, f32x2 packed) + softmax over 9 taps
// + weighted unfold aggregation. One thread = one output pixel.
// ---------------------------------------------------------------------------
template<int YC, int NG, int CPG>
__global__ __launch_bounds__(128)
void mask_agg(const float* __restrict__ y, const float* __restrict__ w2,
              const float* __restrict__ x, float* __restrict__ out)
{
    constexpr int XC = NG * CPG;
    const int pix = blockIdx.x * 128 + threadIdx.x;   // exact grid: BB*HWO/128
    const int b   = pix / HWO;
    const int rem = pix % HWO;
    const int oh  = rem / WO, ow = rem % WO;

    __shared__ __align__(16) float w_s[YC * 12];      // 9 taps + 3 pad (t=9 zero)

    const float* yp = y + (size_t)b * YC * HWO + rem;

    for (int g = 0; g < NG; ++g) {
        for (int idx = threadIdx.x; idx < YC * 12; idx += 128) {
            int t = idx % 12, ic = idx / 12;
            float v = 0.f;
            if (t < 9) v = w2[((size_t)(g * 9 + t)) * YC + ic];
            w_s[idx] = v;
        }
        __syncthreads();

        unsigned long long acc2[5];
        #pragma unroll
        for (int t = 0; t < 5; ++t) acc2[t] = 0ull;

        #pragma unroll 4
        for (int ic = 0; ic < YC; ++ic) {
            float yv = yp[(size_t)ic * HWO];
            unsigned long long yk = pack2(yv);
            const unsigned long long* wp = (const unsigned long long*)&w_s[ic * 12];
            #pragma unroll
            for (int t = 0; t < 5; ++t) ffma2(acc2[t], wp[t], yk);
        }

        float acc[10];
        #pragma unroll
        for (int t = 0; t < 5; ++t) unpack2(acc2[t], acc[2 * t], acc[2 * t + 1]);

        // softmax over the 9 taps
        float m = acc[0];
        #pragma unroll
        for (int t = 1; t < 9; ++t) m = fmaxf(m, acc[t]);
        float e[9], s = 0.f;
        #pragma unroll
        for (int t = 0; t < 9; ++t) { e[t] = __expf(acc[t] - m); s += e[t]; }
        float inv = 1.f / s;
        #pragma unroll
        for (int t = 0; t < 9; ++t) e[t] *= inv;

        // weighted aggregation of the unfold patch
        #pragma unroll
        for (int i = 0; i < CPG; ++i) {
            int c = i * NG + g;
            const float* xc = x + ((size_t)(b * XC + c)) * HH * WW;
            float sum = 0.f;
            #pragma unroll
            for (int kh = 0; kh < 3; ++kh) {
                int ih = 2 * oh + kh - 1;
                #pragma unroll
                for (int kw = 0; kw < 3; ++kw) {
                    int iw = 2 * ow + kw - 1;
                    float xv = 0.f;
                    if ((unsigned)ih < (unsigned)HH && (unsigned)iw < (unsigned)WW)
                        xv = xc[ih * WW + iw];
                    sum += e[kh * 3 + kw] * xv;
                }
            }
            out[((size_t)(b * XC + c)) * HWO + rem] = sum;
        }
        __syncthreads();
    }
}

// ---------------------------------------------------------------------------
// Kernel 3: group-wise correlation volume.
// ---------------------------------------------------------------------------
__global__ __launch_bounds__(160)
void gwc_vol(const float* __restrict__ g8, float* __restrict__ out)
{
    const int h = blockIdx.x;
    const int g = blockIdx.y;
    const int b = blockIdx.z;

    __shared__ float ls[12][WO];
    __shared__ float rs[12][WO];

    for (int idx = threadIdx.x; idx < 2 * 12 * WO; idx += 160) {
        int half = idx / (12 * WO);
        int rem  = idx % (12 * WO);
        int c = rem / WO, w = rem % WO;
        int bb = half == 0 ? b : b + 2;
        float v = g8[(((size_t)bb * 96 + g * 12 + c) * HO + h) * WO + w];
        if (half == 0) ls[c][w] = v; else rs[c][w] = v;
    }
    __syncthreads();

    const int w = threadIdx.x;
    if (w < WO) {
        float lr[12];
        #pragma unroll
        for (int c = 0; c < 12; ++c) lr[c] = ls[c][w];
        for (int d = 0; d < DMAX; ++d) {
            float s = 0.f;
            if (w >= d) {
                #pragma unroll
                for (int c = 0; c < 12; ++c) s += lr[c] * rs[c][w - d];
                s *= (1.f / 12.f);
            }
            out[((((size_t)b * 32 + g) * DMAX + d) * HO + h) * WO + w] = s;
        }
    }
}

// ---------------------------------------------------------------------------
// Kernel 4: concat volume — pure gather into out channels [8, 32).
// ---------------------------------------------------------------------------
__global__ __launch_bounds__(256)
void cat_vol(const float* __restrict__ c8, float* __restrict__ out)
{
    int idx = blockIdx.x * 256 + threadIdx.x;   // exact: 2*24*24*80*144 / 256
    int w = idx % WO; int t = idx / WO;
    int h = t % HO; t /= HO;
    int d = t % DMAX; t /= DMAX;
    int ch = t % 24; int b = t / 24;

    float v = 0.f;
    if (w >= d) {
        v = (ch < 12)
          ? c8[(((size_t)b * 12 + ch) * HO + h) * WO + w]
          : c8[((((size_t)b + 2) * 12 + (ch - 12)) * HO + h) * WO + (w - d)];
    }
    out[((((size_t)b * 32 + 8 + ch) * DMAX + d) * HO + h) * WO + w] = v;
}

// ---------------------------------------------------------------------------
extern "C" void kernel_launch(void* const* d_in, const int* in_sizes, int n_in,
                              void* d_out, int out_size)
{
    const float* gwc_x   = (const float*)d_in[0];
    const float* cat_x   = (const float*)d_in[1];
    const float* g_w1    = (const float*)d_in[2];
    const float* g_bng   = (const float*)d_in[3];
    const float* g_bnb   = (const float*)d_in[4];
    const float* g_bnm   = (const float*)d_in[5];
    const float* g_bnv   = (const float*)d_in[6];
    const float* g_w2    = (const float*)d_in[7];
    const float* c_w1    = (const float*)d_in[8];
    const float* c_bng   = (const float*)d_in[9];
    const float* c_bnb   = (const float*)d_in[10];
    const float* c_bnm   = (const float*)d_in[11];
    const float* c_bnv   = (const float*)d_in[12];
    const float* c_w2    = (const float*)d_in[13];
    float* out = (float*)d_out;

    float *gy, *cy, *g8, *c8;
    cudaGetSymbolAddress((void**)&gy, d_gy);
    cudaGetSymbolAddress((void**)&cy, d_cy);
    cudaGetSymbolAddress((void**)&g8, d_g8);
    cudaGetSymbolAddress((void**)&c8, d_c8);

    // conv1 + BN + LeakyReLU
    conv1_bn_lrelu<96, 192, 64><<<dim3(WO/16, HO/8, BB * 3), 256>>>(
        gwc_x, g_w1, g_bng, g_bnb, g_bnm, g_bnv, gy);
    conv1_bn_lrelu<12, 24, 32><<<dim3(WO/16, HO/8, BB * 1), 256>>>(
        cat_x, c_w1, c_bng, c_bnb, c_bnm, c_bnv, cy);

    // fused 1x1 conv + softmax + unfold aggregation
    mask_agg<192, 16, 6><<<BB * HWO / 128, 128>>>(gy, g_w2, gwc_x, g8);
    mask_agg<24, 12, 1><<<BB * HWO / 128, 128>>>(cy, c_w2, cat_x, c8);

    // cost volumes
    gwc_vol<<<dim3(HO, 8, 2), 160>>>(g8, out);
    cat_vol<<<(2 * 24 * DMAX * HO * WO) / 256, 256>>>(c8, out);
}

// round 4
// speedup vs baseline: 1.3978x; 1.3978x over previous
#include <cuda_runtime.h>
#include <cuda_bf16.h>

// Problem constants
#define BB   4
#define HH   160
#define WW   288
#define HO   80
#define WO   144
#define HWO  (HO*WO)     // 11520
#define DMAX 24
#define EPSV 1e-5f

// Scratch (no allocation allowed -> __device__ globals)
__device__ float d_gy[BB*192*HWO];   // gwc conv1+bn+lrelu output (4,192,80,144)
__device__ float d_cy[BB*24*HWO];    // cat conv1+bn+lrelu output (4,24,80,144)
__device__ float d_g8[BB*96*HWO];    // gwc downsampled features  (4,96,80,144)
__device__ float d_c8[BB*12*HWO];    // cat downsampled features  (4,12,80,144)

// ---- packed f32x2 helpers (sm_100+) ---------------------------------------
__device__ __forceinline__ unsigned long long pack2(float v) {
    unsigned long long r;
    asm("mov.b64 %0, {%1, %1};" : "=l"(r) : "f"(v));
    return r;
}
__device__ __forceinline__ void ffma2(unsigned long long& acc,
                                      unsigned long long a,
                                      unsigned long long b) {
    asm("fma.rn.f32x2 %0, %1, %2, %0;" : "+l"(acc) : "l"(a), "l"(b));
}
__device__ __forceinline__ void unpack2(unsigned long long v, float& lo, float& hi) {
    asm("mov.b64 {%0, %1}, %2;" : "=f"(lo), "=f"(hi) : "l"(v));
}

// ---------------------------------------------------------------------------
// Kernel 1: 3x3 stride-2 pad-1 conv + BN + LeakyReLU(0.1)
// Tile: 8x16 output pixels, OCB output channels per block, ic chunks of 4.
// Software-pipelined: chunk k+1 is fetched into registers while chunk k
// computes from smem, hiding GMEM latency behind the FMA phase.
// ---------------------------------------------------------------------------
template<int CIN, int COUT, int OCB>
__global__ __launch_bounds__(256, 2)
void conv1_bn_lrelu(const float* __restrict__ x, const float* __restrict__ w,
                    const float* __restrict__ bng, const float* __restrict__ bnb,
                    const float* __restrict__ bnm, const float* __restrict__ bnv,
                    float* __restrict__ y)
{
    constexpr int NOC  = (COUT + OCB - 1) / OCB;
    constexpr int OCT  = OCB / 8;                 // oc per thread
    constexpr int NP   = OCT / 2;                 // oc pairs per thread
    constexpr int NCH  = CIN / 4;                 // ic chunks
    constexpr int INEL = 4 * 561;                 // 2244 patch elements/chunk
    constexpr int NIN  = (INEL + 255) / 256;      // 9
    constexpr int WEL  = 36 * OCB;                // weight elements/chunk
    constexpr int NWT  = (WEL + 255) / 256;

    const int bz      = blockIdx.z;
    const int b       = bz / NOC;
    const int oc_base = (bz % NOC) * OCB;
    const int oh0 = blockIdx.y * 8;
    const int ow0 = blockIdx.x * 16;
    const int ih0 = oh0 * 2 - 1;
    const int iw0 = ow0 * 2 - 1;

    __shared__ __align__(16) float in_s[INEL];      // 4 ic x 17h x 33w
    __shared__ __align__(16) float w_s[WEL];        // [ic*9+tap][oc_local]

    const int tid = threadIdx.x;
    const int og  = tid >> 5;
    const int pq  = tid & 31;
    const int ph  = pq >> 2;
    const int pw0 = (pq & 3) * 4;

    // ---- precompute per-thread load descriptors (reused every chunk) ------
    int  in_goff[NIN];  bool in_st[NIN], in_ok[NIN];
    #pragma unroll
    for (int j = 0; j < NIN; ++j) {
        int idx = tid + j * 256;
        in_st[j] = (idx < INEL);
        int ic = idx / 561, rem = idx % 561;
        int ih = rem / 33,  iw  = rem % 33;
        int gh = ih0 + ih,  gw  = iw0 + iw;
        in_ok[j]   = in_st[j] && (unsigned)gh < (unsigned)HH && (unsigned)gw < (unsigned)WW;
        in_goff[j] = in_ok[j] ? (ic * (HH * WW) + gh * WW + gw) : 0;
    }
    int  wt_goff[NWT];  bool wt_st[NWT], wt_ok[NWT];
    #pragma unroll
    for (int j = 0; j < NWT; ++j) {
        int idx = tid + j * 256;
        wt_st[j] = (idx < WEL);
        int oc_l = idx % OCB;
        int r    = idx / OCB;                    // ic*9 + tap
        int oc_g = oc_base + oc_l;
        wt_ok[j]   = wt_st[j] && (oc_g < COUT);
        wt_goff[j] = wt_ok[j] ? (oc_g * (CIN * 9) + r) : 0;
    }

    const float* xb = x + (size_t)b * CIN * HH * WW;

    unsigned long long acc2[NP][4];
    #pragma unroll
    for (int k = 0; k < NP; ++k)
        #pragma unroll
        for (int j = 0; j < 4; ++j) acc2[k][j] = 0ull;

    float rin[NIN], rw[NWT];
    // prologue: fetch chunk 0
    #pragma unroll
    for (int j = 0; j < NIN; ++j)
        rin[j] = in_ok[j] ? __ldg(xb + in_goff[j]) : 0.f;
    #pragma unroll
    for (int j = 0; j < NWT; ++j)
        rw[j] = wt_ok[j] ? __ldg(w + wt_goff[j]) : 0.f;

    for (int c = 0; c < NCH; ++c) {
        __syncthreads();                 // previous compute done -> smem free
        #pragma unroll
        for (int j = 0; j < NIN; ++j)
            if (in_st[j]) in_s[tid + j * 256] = rin[j];
        #pragma unroll
        for (int j = 0; j < NWT; ++j)
            if (wt_st[j]) w_s[tid + j * 256] = rw[j];
        __syncthreads();

        if (c + 1 < NCH) {               // fetch next chunk (overlaps compute)
            const float* xn = xb + (size_t)(c + 1) * 4 * HH * WW;
            const float* wn = w + (size_t)(c + 1) * 4 * 9;
            #pragma unroll
            for (int j = 0; j < NIN; ++j)
                rin[j] = in_ok[j] ? __ldg(xn + in_goff[j]) : 0.f;
            #pragma unroll
            for (int j = 0; j < NWT; ++j)
                rw[j] = wt_ok[j] ? __ldg(wn + wt_goff[j]) : 0.f;
        }

        #pragma unroll
        for (int ic = 0; ic < 4; ++ic) {
            #pragma unroll
            for (int kh = 0; kh < 3; ++kh) {
                const float* ip = &in_s[ic * 561 + (ph * 2 + kh) * 33 + pw0 * 2];
                float iv[9];
                #pragma unroll
                for (int q = 0; q < 9; ++q) iv[q] = ip[q];
                #pragma unroll
                for (int kw = 0; kw < 3; ++kw) {
                    unsigned long long ipk[4];
                    #pragma unroll
                    for (int j = 0; j < 4; ++j) ipk[j] = pack2(iv[2 * j + kw]);
                    const unsigned long long* wp = (const unsigned long long*)
                        &w_s[(ic * 9 + kh * 3 + kw) * OCB + og * OCT];
                    #pragma unroll
                    for (int k = 0; k < NP; ++k) {
                        unsigned long long wv = wp[k];
                        #pragma unroll
                        for (int j = 0; j < 4; ++j) ffma2(acc2[k][j], wv, ipk[j]);
                    }
                }
            }
        }
    }

    // BN + LeakyReLU epilogue
    #pragma unroll
    for (int k = 0; k < NP; ++k) {
        #pragma unroll
        for (int half = 0; half < 2; ++half) {
            int oc_g = oc_base + og * OCT + 2 * k + half;
            if (oc_g < COUT) {
                float sc = bng[oc_g] * rsqrtf(bnv[oc_g] + EPSV);
                float sh = bnb[oc_g] - bnm[oc_g] * sc;
                float* yp = y + (((size_t)b * COUT + oc_g) * HO + oh0 + ph) * WO
                              + ow0 + pw0;
                #pragma unroll
                for (int j = 0; j < 4; ++j) {
                    float lo, hi;
                    unpack2(acc2[k][j], lo, hi);
                    float a = half ? hi : lo;
                    float v = a * sc + sh;
                    v = (v >= 0.f) ? v : 0.1f * v;
                    yp[j] = v;
                }
            }
        }
    }
}

// ---------------------------------------------------------------------------
// Kernel 2: fused 1x1 conv (mask logits, f32x2) + softmax over 9 taps +
// weighted unfold aggregation. One thread = one pixel, one BLOCK = one group
// (grid.y = NG) for 16x more parallelism than the looped version.
// ---------------------------------------------------------------------------
template<int YC, int NG, int CPG>
__global__ __launch_bounds__(128)
void mask_agg(const float* __restrict__ y, const float* __restrict__ w2,
              const float* __restrict__ x, float* __restrict__ out)
{
    constexpr int XC = NG * CPG;
    const int pix = blockIdx.x * 128 + threadIdx.x;   // exact grid
    const int g   = blockIdx.y;
    const int b   = pix / HWO;
    const int rem = pix % HWO;
    const int oh  = rem / WO, ow = rem % WO;

    __shared__ __align__(16) float w_s[YC * 12];      // 9 taps + 3 pad (zeroed)

    for (int idx = threadIdx.x; idx < YC * 12; idx += 128) {
        int t = idx % 12, ic = idx / 12;
        float v = 0.f;
        if (t < 9) v = w2[((size_t)(g * 9 + t)) * YC + ic];
        w_s[idx] = v;
    }
    __syncthreads();

    const float* yp = y + (size_t)b * YC * HWO + rem;

    unsigned long long acc2[5];
    #pragma unroll
    for (int t = 0; t < 5; ++t) acc2[t] = 0ull;

    #pragma unroll 4
    for (int ic = 0; ic < YC; ++ic) {
        float yv = __ldg(yp + (size_t)ic * HWO);
        unsigned long long yk = pack2(yv);
        const unsigned long long* wp = (const unsigned long long*)&w_s[ic * 12];
        #pragma unroll
        for (int t = 0; t < 5; ++t) ffma2(acc2[t], wp[t], yk);
    }

    float acc[10];
    #pragma unroll
    for (int t = 0; t < 5; ++t) unpack2(acc2[t], acc[2 * t], acc[2 * t + 1]);

    // softmax over the 9 taps
    float m = acc[0];
    #pragma unroll
    for (int t = 1; t < 9; ++t) m = fmaxf(m, acc[t]);
    float e[9], s = 0.f;
    #pragma unroll
    for (int t = 0; t < 9; ++t) { e[t] = __expf(acc[t] - m); s += e[t]; }
    float inv = 1.f / s;
    #pragma unroll
    for (int t = 0; t < 9; ++t) e[t] *= inv;

    // weighted aggregation of the unfold patch
    #pragma unroll
    for (int i = 0; i < CPG; ++i) {
        int c = i * NG + g;
        const float* xc = x + ((size_t)(b * XC + c)) * HH * WW;
        float sum = 0.f;
        #pragma unroll
        for (int kh = 0; kh < 3; ++kh) {
            int ih = 2 * oh + kh - 1;
            #pragma unroll
            for (int kw = 0; kw < 3; ++kw) {
                int iw = 2 * ow + kw - 1;
                float xv = 0.f;
                if ((unsigned)ih < (unsigned)HH && (unsigned)iw < (unsigned)WW)
                    xv = __ldg(xc + ih * WW + iw);
                sum += e[kh * 3 + kw] * xv;
            }
        }
        out[((size_t)(b * XC + c)) * HWO + rem] = sum;
    }
}

// ---------------------------------------------------------------------------
// Kernel 3: group-wise correlation volume.
// ---------------------------------------------------------------------------
__global__ __launch_bounds__(160)
void gwc_vol(const float* __restrict__ g8, float* __restrict__ out)
{
    const int h = blockIdx.x;
    const int g = blockIdx.y;
    const int b = blockIdx.z;

    __shared__ float ls[12][WO];
    __shared__ float rs[12][WO];

    for (int idx = threadIdx.x; idx < 2 * 12 * WO; idx += 160) {
        int half = idx / (12 * WO);
        int rem  = idx % (12 * WO);
        int c = rem / WO, w = rem % WO;
        int bb = half == 0 ? b : b + 2;
        float v = g8[(((size_t)bb * 96 + g * 12 + c) * HO + h) * WO + w];
        if (half == 0) ls[c][w] = v; else rs[c][w] = v;
    }
    __syncthreads();

    const int w = threadIdx.x;
    if (w < WO) {
        float lr[12];
        #pragma unroll
        for (int c = 0; c < 12; ++c) lr[c] = ls[c][w];
        for (int d = 0; d < DMAX; ++d) {
            float s = 0.f;
            if (w >= d) {
                #pragma unroll
                for (int c = 0; c < 12; ++c) s += lr[c] * rs[c][w - d];
                s *= (1.f / 12.f);
            }
            out[((((size_t)b * 32 + g) * DMAX + d) * HO + h) * WO + w] = s;
        }
    }
}

// ---------------------------------------------------------------------------
// Kernel 4: concat volume — pure gather into out channels [8, 32).
// ---------------------------------------------------------------------------
__global__ __launch_bounds__(256)
void cat_vol(const float* __restrict__ c8, float* __restrict__ out)
{
    int idx = blockIdx.x * 256 + threadIdx.x;   // exact: 2*24*24*80*144 / 256
    int w = idx % WO; int t = idx / WO;
    int h = t % HO; t /= HO;
    int d = t % DMAX; t /= DMAX;
    int ch = t % 24; int b = t / 24;

    float v = 0.f;
    if (w >= d) {
        v = (ch < 12)
          ? c8[(((size_t)b * 12 + ch) * HO + h) * WO + w]
          : c8[((((size_t)b + 2) * 12 + (ch - 12)) * HO + h) * WO + (w - d)];
    }
    out[((((size_t)b * 32 + 8 + ch) * DMAX + d) * HO + h) * WO + w] = v;
}

// ---------------------------------------------------------------------------
extern "C" void kernel_launch(void* const* d_in, const int* in_sizes, int n_in,
                              void* d_out, int out_size)
{
    const float* gwc_x   = (const float*)d_in[0];
    const float* cat_x   = (const float*)d_in[1];
    const float* g_w1    = (const float*)d_in[2];
    const float* g_bng   = (const float*)d_in[3];
    const float* g_bnb   = (const float*)d_in[4];
    const float* g_bnm   = (const float*)d_in[5];
    const float* g_bnv   = (const float*)d_in[6];
    const float* g_w2    = (const float*)d_in[7];
    const float* c_w1    = (const float*)d_in[8];
    const float* c_bng   = (const float*)d_in[9];
    const float* c_bnb   = (const float*)d_in[10];
    const float* c_bnm   = (const float*)d_in[11];
    const float* c_bnv   = (const float*)d_in[12];
    const float* c_w2    = (const float*)d_in[13];
    float* out = (float*)d_out;

    float *gy, *cy, *g8, *c8;
    cudaGetSymbolAddress((void**)&gy, d_gy);
    cudaGetSymbolAddress((void**)&cy, d_cy);
    cudaGetSymbolAddress((void**)&g8, d_g8);
    cudaGetSymbolAddress((void**)&c8, d_c8);

    // conv1 + BN + LeakyReLU (software pipelined)
    conv1_bn_lrelu<96, 192, 64><<<dim3(WO/16, HO/8, BB * 3), 256>>>(
        gwc_x, g_w1, g_bng, g_bnb, g_bnm, g_bnv, gy);
    conv1_bn_lrelu<12, 24, 32><<<dim3(WO/16, HO/8, BB * 1), 256>>>(
        cat_x, c_w1, c_bng, c_bnb, c_bnm, c_bnv, cy);

    // fused 1x1 conv + softmax + unfold aggregation (one group per block)
    mask_agg<192, 16, 6><<<dim3(BB * HWO / 128, 16), 128>>>(gy, g_w2, gwc_x, g8);
    mask_agg<24, 12, 1><<<dim3(BB * HWO / 128, 12), 128>>>(cy, c_w2, cat_x, c8);

    // cost volumes
    gwc_vol<<<dim3(HO, 8, 2), 160>>>(g8, out);
    cat_vol<<<(2 * 24 * DMAX * HO * WO) / 256, 256>>>(c8, out);
}